// round 13
// baseline (speedup 1.0000x reference)
#include <cuda_runtime.h>
#include <cuda_bf16.h>
#include <cstdint>

#define NN 20000
#define EE 320000
#define FF 512
#define HH 8
#define DD 64
#define HD 512           // HH*DD
#define LRELU 0.2f
#define EPSV 1e-16f

#define TM 128
#define TN 128
#define A_BYTES 32768            // 128 rows x 128 bf16 (two 128B half-rows)
#define STAGE_BYTES 65536        // A tile + B tile
#define NSTAGE 12                // 4 K-chunks(128) x 3 hi/lo combos

// ---------------- scratch (static device globals; no allocs) ----------------
__device__ float g_he[NN * HD];
__device__ float g_hr[NN * HD];
__device__ __nv_bfloat16 g_xh[NN * FF];
__device__ __nv_bfloat16 g_xl[NN * FF];
__device__ __nv_bfloat16 g_Wbh[2][FF * HD];   // [mat][n][k]  (n = h*64+d, k = f)
__device__ __nv_bfloat16 g_Wbl[2][FF * HD];
__device__ float g_sS[NN * HH];
__device__ float g_sD[NN * HH];
__device__ float g_pD[NN * HH];
__device__ int   g_deg[NN];
__device__ int   g_off[NN + 1];
__device__ int   g_cur[NN];
__device__ int   g_srcs[EE];
__device__ int   g_dsts[EE];
__device__ float g_att[EE * HH];   // layout [edge][head]
__device__ int   g_is64;

// ---------------- small helpers ----------------
__device__ __forceinline__ uint32_t smem_u32(const void* p) {
    uint32_t a;
    asm("{ .reg .u64 t; cvta.to.shared.u64 t, %1; cvt.u32.u64 %0, t; }" : "=r"(a) : "l"(p));
    return a;
}

__device__ __forceinline__ void cp16(uint32_t dst, const void* src, int srcsize) {
    asm volatile("cp.async.cg.shared.global [%0], [%1], 16, %2;"
                 :: "r"(dst), "l"(src), "r"(srcsize) : "memory");
}

#define SWZ(o) ((o) ^ (((o) >> 3) & 0x70))

#define LDSM4(r, a) \
    asm volatile("ldmatrix.sync.aligned.m8n8.x4.shared.b16 {%0,%1,%2,%3}, [%4];" \
                 : "=r"((r)[0]), "=r"((r)[1]), "=r"((r)[2]), "=r"((r)[3]) : "r"(a))

#define MMA16816(c, a, b0, b1) \
    asm volatile("mma.sync.aligned.m16n8k16.row.col.f32.bf16.bf16.f32 " \
                 "{%0,%1,%2,%3},{%4,%5,%6,%7},{%8,%9},{%0,%1,%2,%3};" \
                 : "+f"((c)[0]), "+f"((c)[1]), "+f"((c)[2]), "+f"((c)[3]) \
                 : "r"((a)[0]), "r"((a)[1]), "r"((a)[2]), "r"((a)[3]), \
                   "r"(b0), "r"(b1))

// ---------------- dtype probe ----------------
__global__ void detect_k(const int* __restrict__ w) {
    if (threadIdx.x == 0 && blockIdx.x == 0) {
        int ornz = 0;
        for (int i = 1; i < 256; i += 2) ornz |= w[i];
        g_is64 = (ornz == 0) ? 1 : 0;
    }
}

__device__ __forceinline__ int load_idx(const void* ei, int which, int e) {
    if (g_is64) return (int)((const long long*)ei)[(long)which * EE + e];
    return ((const int*)ei)[which * EE + e];
}

// ---------------- x -> bf16 hi/lo ----------------
__global__ void cvt_x(const float* __restrict__ x) {
    int i = blockIdx.x * blockDim.x + threadIdx.x;
    if (i >= NN * FF / 4) return;
    float4 v = ((const float4*)x)[i];
    __nv_bfloat16 h0 = __float2bfloat16_rn(v.x);
    __nv_bfloat16 h1 = __float2bfloat16_rn(v.y);
    __nv_bfloat16 h2 = __float2bfloat16_rn(v.z);
    __nv_bfloat16 h3 = __float2bfloat16_rn(v.w);
    __nv_bfloat16 l0 = __float2bfloat16_rn(v.x - __bfloat162float(h0));
    __nv_bfloat16 l1 = __float2bfloat16_rn(v.y - __bfloat162float(h1));
    __nv_bfloat16 l2 = __float2bfloat16_rn(v.z - __bfloat162float(h2));
    __nv_bfloat16 l3 = __float2bfloat16_rn(v.w - __bfloat162float(h3));
    ((__nv_bfloat162*)g_xh)[i * 2 + 0] = __nv_bfloat162(h0, h1);
    ((__nv_bfloat162*)g_xh)[i * 2 + 1] = __nv_bfloat162(h2, h3);
    ((__nv_bfloat162*)g_xl)[i * 2 + 0] = __nv_bfloat162(l0, l1);
    ((__nv_bfloat162*)g_xl)[i * 2 + 1] = __nv_bfloat162(l2, l3);
}

// ---------------- W -> bf16 hi/lo, transposed to [n][k] ---------------------
__global__ void prep_wb(const float* __restrict__ We, const float* __restrict__ Wr) {
    int idx = blockIdx.x * blockDim.x + threadIdx.x;
    if (idx >= 2 * FF * HD) return;
    int which = idx / (FF * HD);
    int rem = idx - which * (FF * HD);
    int n = rem >> 9;        // output column = h*64+d
    int k = rem & 511;       // input feature f
    int h = n >> 6, d = n & 63;
    const float* W = which ? Wr : We;
    float v = W[h * (FF * DD) + k * DD + d];
    __nv_bfloat16 hi = __float2bfloat16_rn(v);
    __nv_bfloat16 lo = __float2bfloat16_rn(v - __bfloat162float(hi));
    g_Wbh[which][n * FF + k] = hi;
    g_Wbl[which][n * FF + k] = lo;
}

// ---------------- stage loader: A 128x128bf16 + B 128x128bf16 ---------------
// Stage layout: two half-K blocks, each 128 rows x 128B, SW128-swizzled.
__device__ __forceinline__ void load_stage(int s, int tid, int mBase, int nBase,
                                           uint32_t smem_base,
                                           const __nv_bfloat16* Wh,
                                           const __nv_bfloat16* Wl) {
    int combo = s >> 2, kc2 = s & 3;
    const __nv_bfloat16* Asrc = (combo < 2) ? g_xh : g_xl;
    const __nv_bfloat16* Bsrc = (combo == 1) ? Wl : Wh;
    uint32_t abase = smem_base + (s % 3) * STAGE_BYTES;
    uint32_t bbase = abase + A_BYTES;
#pragma unroll
    for (int i = tid; i < 2048; i += 256) {
        int row = i >> 4, r = i & 15, half = r >> 3, c = r & 7;
        int gm = mBase + row;
        uint32_t dst = abase + half * 16384 + SWZ(row * 128 + c * 16);
        size_t off = (gm < NN) ? ((size_t)gm * 1024 + kc2 * 256 + half * 128 + c * 16) : 0;
        cp16(dst, (const char*)Asrc + off, gm < NN ? 16 : 0);
    }
#pragma unroll
    for (int i = tid; i < 2048; i += 256) {
        int row = i >> 4, r = i & 15, half = r >> 3, c = r & 7;
        int n = nBase + row;
        uint32_t dst = bbase + half * 16384 + SWZ(row * 128 + c * 16);
        cp16(dst, (const char*)Bsrc + ((size_t)n * 1024 + kc2 * 256 + half * 128 + c * 16), 16);
    }
    asm volatile("cp.async.commit_group;" ::: "memory");
}

// ---------------- bf16 mma.sync GEMM: C = xh*Wh + xh*Wl + xl*Wh -------------
__global__ __launch_bounds__(256, 1) void mma_k() {
    extern __shared__ char smem[];
    int tid = threadIdx.x, wid = tid >> 5, lane = tid & 31;
    int mBase = blockIdx.x * TM;
    int nBase = blockIdx.y * TN;
    int mat = blockIdx.z;
    const __nv_bfloat16* Wh = g_Wbh[mat];
    const __nv_bfloat16* Wl = g_Wbl[mat];
    float* C = mat ? g_hr : g_he;

    uint32_t smem_base = smem_u32(smem);

    int warp_m = wid >> 2;          // 0..1  -> m offset *64
    int warp_n = wid & 3;           // 0..3  -> n offset *32
    int g = lane >> 3, lr = lane & 7;

    int arow = warp_m * 64 + (g & 1) * 8 + lr;     // + im*16
    int abyt = (g >> 1) * 16;
    int brow = warp_n * 32 + (g >> 1) * 8 + lr;    // + jp*16
    int bbyt = (g & 1) * 16;

    float acc[16][4];
#pragma unroll
    for (int i = 0; i < 16; i++)
#pragma unroll
        for (int j = 0; j < 4; j++) acc[i][j] = 0.f;

    load_stage(0, tid, mBase, nBase, smem_base, Wh, Wl);
    load_stage(1, tid, mBase, nBase, smem_base, Wh, Wl);
    load_stage(2, tid, mBase, nBase, smem_base, Wh, Wl);

    for (int s = 0; s < NSTAGE; s++) {
        if (s <= NSTAGE - 3)      asm volatile("cp.async.wait_group 2;" ::: "memory");
        else if (s == NSTAGE - 2) asm volatile("cp.async.wait_group 1;" ::: "memory");
        else                      asm volatile("cp.async.wait_group 0;" ::: "memory");
        __syncthreads();

        uint32_t abase = smem_base + (s % 3) * STAGE_BYTES;
        uint32_t bbase = abase + A_BYTES;

#pragma unroll
        for (int ks = 0; ks < 8; ks++) {
            uint32_t ab = abase + (ks >> 2) * 16384;
            uint32_t bb = bbase + (ks >> 2) * 16384;
            int ksi = ks & 3;
            uint32_t af[4][4], bf[2][4];
#pragma unroll
            for (int im = 0; im < 4; im++) {
                uint32_t a = ab + SWZ((arow + im * 16) * 128 + ksi * 32 + abyt);
                LDSM4(af[im], a);
            }
#pragma unroll
            for (int jp = 0; jp < 2; jp++) {
                uint32_t b = bb + SWZ((brow + jp * 16) * 128 + ksi * 32 + bbyt);
                LDSM4(bf[jp], b);
            }
#pragma unroll
            for (int im = 0; im < 4; im++) {
#pragma unroll
                for (int jn = 0; jn < 4; jn++) {
                    uint32_t b0 = bf[jn >> 1][(jn & 1) * 2 + 0];
                    uint32_t b1 = bf[jn >> 1][(jn & 1) * 2 + 1];
                    MMA16816(acc[im * 4 + jn], af[im], b0, b1);
                }
            }
        }
        __syncthreads();

        int t = s + 3;
        if (t < NSTAGE) load_stage(t, tid, mBase, nBase, smem_base, Wh, Wl);
    }

    // epilogue
    int q = lane >> 2, rpair = lane & 3;
#pragma unroll
    for (int im = 0; im < 4; im++) {
        int r0 = mBase + warp_m * 64 + im * 16 + q;
        int r1 = r0 + 8;
#pragma unroll
        for (int jn = 0; jn < 4; jn++) {
            int col = nBase + warp_n * 32 + jn * 8 + rpair * 2;
            float* c = acc[im * 4 + jn];
            if (r0 < NN) *(float2*)(C + (size_t)r0 * HD + col) = make_float2(c[0], c[1]);
            if (r1 < NN) *(float2*)(C + (size_t)r1 * HD + col) = make_float2(c[2], c[3]);
        }
    }
}

// ---------------- per-node scalars: thread per (n,h) ------------------------
__global__ __launch_bounds__(256) void node_scalar(const float* __restrict__ a) {
    __shared__ float sSrc[HD], sDst[HD], sDif[HD];
    int tid = threadIdx.x;
    for (int i = tid; i < HD; i += 256) {
        int h = i >> 6, d = i & 63;
        sSrc[i] = a[h * 320 + d];
        sDst[i] = a[h * 320 + DD + d];
        sDif[i] = a[h * 320 + 2 * DD + d];
    }
    __syncthreads();

    int g = blockIdx.x * 256 + tid;
    if (g >= NN * HH) return;
    int n = g >> 3, h = g & 7;
    const float4* he = (const float4*)(g_he + (size_t)n * HD + h * DD);
    const float4* hr = (const float4*)(g_hr + (size_t)n * HD + h * DD);
    const float4* cs = (const float4*)(sSrc + h * DD);
    const float4* cd = (const float4*)(sDst + h * DD);
    const float4* cf = (const float4*)(sDif + h * DD);

    float s1 = 0.f, s2 = 0.f, s3 = 0.f;
#pragma unroll
    for (int i = 0; i < 16; i++) {
        float4 e = he[i], r = hr[i], a1 = cs[i], a2 = cd[i], a3 = cf[i];
        s1 = fmaf(e.x, a1.x, fmaf(e.y, a1.y, fmaf(e.z, a1.z, fmaf(e.w, a1.w, s1))));
        s2 = fmaf(e.x, a2.x, fmaf(e.y, a2.y, fmaf(e.z, a2.z, fmaf(e.w, a2.w, s2))));
        s3 = fmaf(r.x, a3.x, fmaf(r.y, a3.y, fmaf(r.z, a3.z, fmaf(r.w, a3.w, s3))));
    }
    g_sS[g] = s1;
    g_sD[g] = s2;
    g_pD[g] = s3;
}

// ---------------- CSR build ----------------
__global__ void zero_deg() {
    int i = blockIdx.x * blockDim.x + threadIdx.x;
    if (i < NN) g_deg[i] = 0;
}

__global__ void hist_k(const void* __restrict__ ei) {
    int e = blockIdx.x * blockDim.x + threadIdx.x;
    if (e >= EE) return;
    atomicAdd(&g_deg[load_idx(ei, 0, e)], 1);
}

__global__ void scan_k() {
    __shared__ int wsum[32];
    __shared__ int s_carry;
    int tid = threadIdx.x, lane = tid & 31, wid = tid >> 5;
    if (tid == 0) s_carry = 0;
    __syncthreads();
    for (int base = 0; base < NN; base += 1024) {
        int i = base + tid;
        int x = (i < NN) ? g_deg[i] : 0;
#pragma unroll
        for (int o = 1; o < 32; o <<= 1) {
            int t = __shfl_up_sync(0xffffffffu, x, o);
            if (lane >= o) x += t;
        }
        if (lane == 31) wsum[wid] = x;
        __syncthreads();
        if (wid == 0) {
            int y = wsum[lane];
#pragma unroll
            for (int o = 1; o < 32; o <<= 1) {
                int t = __shfl_up_sync(0xffffffffu, y, o);
                if (lane >= o) y += t;
            }
            wsum[lane] = y;
        }
        __syncthreads();
        int c = s_carry;
        int incl = x + (wid ? wsum[wid - 1] : 0) + c;
        if (i < NN) g_off[i + 1] = incl;
        __syncthreads();
        if (tid == 1023) s_carry = incl;
        __syncthreads();
    }
    if (threadIdx.x == 0) g_off[0] = 0;
}

__global__ void copy_cur() {
    int i = blockIdx.x * blockDim.x + threadIdx.x;
    if (i < NN) g_cur[i] = g_off[i];
}

__global__ void scatter_k(const void* __restrict__ ei) {
    int e = blockIdx.x * blockDim.x + threadIdx.x;
    if (e >= EE) return;
    int s = load_idx(ei, 0, e);
    int t = load_idx(ei, 1, e);
    int p = atomicAdd(&g_cur[s], 1);
    g_srcs[p] = s;
    g_dsts[p] = t;
}

// ---------------- per-edge scores: thread per (edge, head) ------------------
__global__ __launch_bounds__(256) void score_k(const float* __restrict__ a) {
    __shared__ float sAbs[HD], sPrd[HD];
    int tid = threadIdx.x;
    for (int i = tid; i < HD; i += 256) {
        int h = i >> 6, d = i & 63;
        sAbs[i] = a[h * 320 + 3 * DD + d];
        sPrd[i] = a[h * 320 + 4 * DD + d];
    }
    __syncthreads();

    int g = blockIdx.x * 256 + tid;     // g = p*8 + h
    if (g >= EE * HH) return;
    int p = g >> 3, h = g & 7;
    int s = g_srcs[p], t = g_dsts[p];
    const float4* rs = (const float4*)(g_hr + (size_t)s * HD + h * DD);
    const float4* rt = (const float4*)(g_hr + (size_t)t * HD + h * DD);
    const float4* ca = (const float4*)(sAbs + h * DD);
    const float4* cp = (const float4*)(sPrd + h * DD);

    float accA = 0.f, accP = 0.f;
#pragma unroll
    for (int i = 0; i < 16; i++) {
        float4 vs = rs[i], vt = rt[i], aa = ca[i], pp = cp[i];
        accA = fmaf(aa.x, fabsf(vt.x - vs.x), accA);
        accA = fmaf(aa.y, fabsf(vt.y - vs.y), accA);
        accA = fmaf(aa.z, fabsf(vt.z - vs.z), accA);
        accA = fmaf(aa.w, fabsf(vt.w - vs.w), accA);
        accP = fmaf(pp.x * vs.x, vt.x, accP);
        accP = fmaf(pp.y * vs.y, vt.y, accP);
        accP = fmaf(pp.z * vs.z, vt.z, accP);
        accP = fmaf(pp.w * vs.w, vt.w, accP);
    }

    float sc = g_sS[s * HH + h] + g_sD[t * HH + h] + g_pD[t * HH + h]
             - g_pD[s * HH + h] + accA + accP;
    g_att[g] = sc > 0.f ? sc : LRELU * sc;
}

// ---------------- segment softmax: warp per node, all heads at once ---------
__global__ void softmax_k() {
    int w = (blockIdx.x * blockDim.x + threadIdx.x) >> 5;
    int lane = threadIdx.x & 31;
    if (w >= NN) return;
    int b8 = g_off[w] * 8, e8 = g_off[w + 1] * 8;
    if (b8 == e8) return;

    // lane's head = lane & 7 (stride 32 preserves h since 8 | 32)
    float m = -3.4e38f;
    for (int i = b8 + lane; i < e8; i += 32) m = fmaxf(m, g_att[i]);
    m = fmaxf(m, __shfl_xor_sync(0xffffffffu, m, 8));
    m = fmaxf(m, __shfl_xor_sync(0xffffffffu, m, 16));

    float sum = 0.f;
    for (int i = b8 + lane; i < e8; i += 32) {
        float e = expf(g_att[i] - m);
        g_att[i] = e;
        sum += e;
    }
    sum += __shfl_xor_sync(0xffffffffu, sum, 8);
    sum += __shfl_xor_sync(0xffffffffu, sum, 16);
    float inv = 1.f / (sum + EPSV);
    for (int i = b8 + lane; i < e8; i += 32) g_att[i] *= inv;
}

// ---------------- aggregation: block per node, float4 per thread ------------
__global__ __launch_bounds__(128) void agg_k(float* __restrict__ out) {
    int n = blockIdx.x;
    int tid = threadIdx.x;
    int h = tid >> 4;                 // (tid*4) / 64
    int beg = g_off[n], end = g_off[n + 1];
    float4 acc = make_float4(0.f, 0.f, 0.f, 0.f);
    for (int p = beg; p < end; p++) {
        int t = g_dsts[p];
        float av = g_att[p * 8 + h];
        float4 v = ((const float4*)(g_he + (size_t)t * HD))[tid];
        acc.x = fmaf(av, v.x, acc.x);
        acc.y = fmaf(av, v.y, acc.y);
        acc.z = fmaf(av, v.z, acc.z);
        acc.w = fmaf(av, v.w, acc.w);
    }
    ((float4*)(out + (size_t)n * HD))[tid] = acc;
}

// ---------------- launch ----------------
extern "C" void kernel_launch(void* const* d_in, const int* in_sizes, int n_in,
                              void* d_out, int out_size) {
    const float* x  = (const float*)d_in[0];
    const void*  ei = d_in[1];
    const float* We = (const float*)d_in[2];
    const float* Wr = (const float*)d_in[3];
    const float* a  = (const float*)d_in[4];
    float* out = (float*)d_out;

    static int smem_set = 0;
    if (!smem_set) {
        cudaFuncSetAttribute(mma_k, cudaFuncAttributeMaxDynamicSharedMemorySize,
                             3 * STAGE_BYTES);
        smem_set = 1;
    }

    detect_k<<<1, 32>>>((const int*)ei);
    prep_wb<<<(2 * FF * HD + 255) / 256, 256>>>(We, Wr);
    cvt_x<<<(NN * FF / 4 + 255) / 256, 256>>>(x);

    dim3 gg((NN + TM - 1) / TM, HD / TN, 2);
    mma_k<<<gg, 256, 3 * STAGE_BYTES>>>();

    node_scalar<<<(NN * HH + 255) / 256, 256>>>(a);

    zero_deg<<<(NN + 255) / 256, 256>>>();
    hist_k<<<(EE + 255) / 256, 256>>>(ei);
    scan_k<<<1, 1024>>>();
    copy_cur<<<(NN + 255) / 256, 256>>>();
    scatter_k<<<(EE + 255) / 256, 256>>>(ei);

    score_k<<<(EE * HH + 255) / 256, 256>>>(a);
    softmax_k<<<(NN * 32 + 255) / 256, 256>>>();
    agg_k<<<NN, 128>>>(out);
}

// round 16
// speedup vs baseline: 1.7716x; 1.7716x over previous
#include <cuda_runtime.h>
#include <cuda_bf16.h>
#include <cstdint>

#define NN 20000
#define EE 320000
#define FF 512
#define HH 8
#define DD 64
#define HD 512           // HH*DD
#define LRELU 0.2f
#define EPSV 1e-16f

#define TM 128
#define TN 128
#define A_BYTES 32768            // 128 rows x 128 bf16 (two 128B half-rows)
#define STAGE_BYTES 65536        // A tile + B tile
#define NSTAGE 12                // 4 K-chunks(128) x 3 hi/lo combos

// ---------------- scratch (static device globals; no allocs) ----------------
__device__ float g_he[NN * HD];
__device__ float g_hr[NN * HD];
__device__ __nv_bfloat16 g_xh[NN * FF];
__device__ __nv_bfloat16 g_xl[NN * FF];
__device__ __nv_bfloat16 g_Wbh[2][FF * HD];   // [mat][n][k]  (n = h*64+d, k = f)
__device__ __nv_bfloat16 g_Wbl[2][FF * HD];
__device__ float g_sS[NN * HH];
__device__ float g_sD[NN * HH];
__device__ float g_pD[NN * HH];
__device__ int   g_deg[NN];
__device__ int   g_off[NN + 1];
__device__ int   g_cur[NN];
__device__ int   g_srcs[EE];
__device__ int   g_dsts[EE];
__device__ float g_att[EE * HH];   // layout [edge][head]
__device__ int   g_is64;

// ---------------- small helpers ----------------
__device__ __forceinline__ uint32_t smem_u32(const void* p) {
    uint32_t a;
    asm("{ .reg .u64 t; cvta.to.shared.u64 t, %1; cvt.u32.u64 %0, t; }" : "=r"(a) : "l"(p));
    return a;
}

__device__ __forceinline__ void cp16(uint32_t dst, const void* src, int srcsize) {
    asm volatile("cp.async.cg.shared.global [%0], [%1], 16, %2;"
                 :: "r"(dst), "l"(src), "r"(srcsize) : "memory");
}

#define SWZ(o) ((o) ^ (((o) >> 3) & 0x70))

#define LDSM4(r, a) \
    asm volatile("ldmatrix.sync.aligned.m8n8.x4.shared.b16 {%0,%1,%2,%3}, [%4];" \
                 : "=r"((r)[0]), "=r"((r)[1]), "=r"((r)[2]), "=r"((r)[3]) : "r"(a))

#define MMA16816(c, a, b0, b1) \
    asm volatile("mma.sync.aligned.m16n8k16.row.col.f32.bf16.bf16.f32 " \
                 "{%0,%1,%2,%3},{%4,%5,%6,%7},{%8,%9},{%0,%1,%2,%3};" \
                 : "+f"((c)[0]), "+f"((c)[1]), "+f"((c)[2]), "+f"((c)[3]) \
                 : "r"((a)[0]), "r"((a)[1]), "r"((a)[2]), "r"((a)[3]), \
                   "r"(b0), "r"(b1))

// ---------------- dtype probe ----------------
__global__ void detect_k(const int* __restrict__ w) {
    if (threadIdx.x == 0 && blockIdx.x == 0) {
        int ornz = 0;
        for (int i = 1; i < 256; i += 2) ornz |= w[i];
        g_is64 = (ornz == 0) ? 1 : 0;
    }
}

__device__ __forceinline__ int load_idx(const void* ei, int which, int e) {
    if (g_is64) return (int)((const long long*)ei)[(long)which * EE + e];
    return ((const int*)ei)[which * EE + e];
}

// ---------------- x -> bf16 hi/lo ----------------
__global__ void cvt_x(const float* __restrict__ x) {
    int i = blockIdx.x * blockDim.x + threadIdx.x;
    if (i >= NN * FF / 4) return;
    float4 v = ((const float4*)x)[i];
    __nv_bfloat16 h0 = __float2bfloat16_rn(v.x);
    __nv_bfloat16 h1 = __float2bfloat16_rn(v.y);
    __nv_bfloat16 h2 = __float2bfloat16_rn(v.z);
    __nv_bfloat16 h3 = __float2bfloat16_rn(v.w);
    __nv_bfloat16 l0 = __float2bfloat16_rn(v.x - __bfloat162float(h0));
    __nv_bfloat16 l1 = __float2bfloat16_rn(v.y - __bfloat162float(h1));
    __nv_bfloat16 l2 = __float2bfloat16_rn(v.z - __bfloat162float(h2));
    __nv_bfloat16 l3 = __float2bfloat16_rn(v.w - __bfloat162float(h3));
    ((__nv_bfloat162*)g_xh)[i * 2 + 0] = __nv_bfloat162(h0, h1);
    ((__nv_bfloat162*)g_xh)[i * 2 + 1] = __nv_bfloat162(h2, h3);
    ((__nv_bfloat162*)g_xl)[i * 2 + 0] = __nv_bfloat162(l0, l1);
    ((__nv_bfloat162*)g_xl)[i * 2 + 1] = __nv_bfloat162(l2, l3);
}

// ---------------- W -> bf16 hi/lo, transposed to [n][k] ---------------------
__global__ void prep_wb(const float* __restrict__ We, const float* __restrict__ Wr) {
    int idx = blockIdx.x * blockDim.x + threadIdx.x;
    if (idx >= 2 * FF * HD) return;
    int which = idx / (FF * HD);
    int rem = idx - which * (FF * HD);
    int n = rem >> 9;        // output column = h*64+d
    int k = rem & 511;       // input feature f
    int h = n >> 6, d = n & 63;
    const float* W = which ? Wr : We;
    float v = W[h * (FF * DD) + k * DD + d];
    __nv_bfloat16 hi = __float2bfloat16_rn(v);
    __nv_bfloat16 lo = __float2bfloat16_rn(v - __bfloat162float(hi));
    g_Wbh[which][n * FF + k] = hi;
    g_Wbl[which][n * FF + k] = lo;
}

// ---------------- stage loader: A 128x128bf16 + B 128x128bf16 ---------------
__device__ __forceinline__ void load_stage(int s, int tid, int mBase, int nBase,
                                           uint32_t smem_base,
                                           const __nv_bfloat16* Wh,
                                           const __nv_bfloat16* Wl) {
    int combo = s >> 2, kc2 = s & 3;
    const __nv_bfloat16* Asrc = (combo < 2) ? g_xh : g_xl;
    const __nv_bfloat16* Bsrc = (combo == 1) ? Wl : Wh;
    uint32_t abase = smem_base + (s % 3) * STAGE_BYTES;
    uint32_t bbase = abase + A_BYTES;
#pragma unroll
    for (int i = tid; i < 2048; i += 256) {
        int row = i >> 4, r = i & 15, half = r >> 3, c = r & 7;
        int gm = mBase + row;
        uint32_t dst = abase + half * 16384 + SWZ(row * 128 + c * 16);
        size_t off = (gm < NN) ? ((size_t)gm * 1024 + kc2 * 256 + half * 128 + c * 16) : 0;
        cp16(dst, (const char*)Asrc + off, gm < NN ? 16 : 0);
    }
#pragma unroll
    for (int i = tid; i < 2048; i += 256) {
        int row = i >> 4, r = i & 15, half = r >> 3, c = r & 7;
        int n = nBase + row;
        uint32_t dst = bbase + half * 16384 + SWZ(row * 128 + c * 16);
        cp16(dst, (const char*)Bsrc + ((size_t)n * 1024 + kc2 * 256 + half * 128 + c * 16), 16);
    }
    asm volatile("cp.async.commit_group;" ::: "memory");
}

// ---------------- bf16 mma.sync GEMM: C = xh*Wh + xh*Wl + xl*Wh -------------
__global__ __launch_bounds__(256, 1) void mma_k() {
    extern __shared__ char smem[];
    int tid = threadIdx.x, wid = tid >> 5, lane = tid & 31;
    int mBase = blockIdx.x * TM;
    int nBase = blockIdx.y * TN;
    int mat = blockIdx.z;
    const __nv_bfloat16* Wh = g_Wbh[mat];
    const __nv_bfloat16* Wl = g_Wbl[mat];
    float* C = mat ? g_hr : g_he;

    uint32_t smem_base = smem_u32(smem);

    int warp_m = wid >> 2;          // 0..1  -> m offset *64
    int warp_n = wid & 3;           // 0..3  -> n offset *32
    int g = lane >> 3, lr = lane & 7;

    int arow = warp_m * 64 + (g & 1) * 8 + lr;     // + im*16
    int abyt = (g >> 1) * 16;
    int brow = warp_n * 32 + (g >> 1) * 8 + lr;    // + jp*16
    int bbyt = (g & 1) * 16;

    float acc[16][4];
#pragma unroll
    for (int i = 0; i < 16; i++)
#pragma unroll
        for (int j = 0; j < 4; j++) acc[i][j] = 0.f;

    load_stage(0, tid, mBase, nBase, smem_base, Wh, Wl);
    load_stage(1, tid, mBase, nBase, smem_base, Wh, Wl);
    load_stage(2, tid, mBase, nBase, smem_base, Wh, Wl);

    for (int s = 0; s < NSTAGE; s++) {
        if (s <= NSTAGE - 3)      asm volatile("cp.async.wait_group 2;" ::: "memory");
        else if (s == NSTAGE - 2) asm volatile("cp.async.wait_group 1;" ::: "memory");
        else                      asm volatile("cp.async.wait_group 0;" ::: "memory");
        __syncthreads();

        uint32_t abase = smem_base + (s % 3) * STAGE_BYTES;
        uint32_t bbase = abase + A_BYTES;

#pragma unroll
        for (int ks = 0; ks < 8; ks++) {
            uint32_t ab = abase + (ks >> 2) * 16384;
            uint32_t bb = bbase + (ks >> 2) * 16384;
            int ksi = ks & 3;
            uint32_t af[4][4], bf[2][4];
#pragma unroll
            for (int im = 0; im < 4; im++) {
                uint32_t a = ab + SWZ((arow + im * 16) * 128 + ksi * 32 + abyt);
                LDSM4(af[im], a);
            }
#pragma unroll
            for (int jp = 0; jp < 2; jp++) {
                uint32_t b = bb + SWZ((brow + jp * 16) * 128 + ksi * 32 + bbyt);
                LDSM4(bf[jp], b);
            }
#pragma unroll
            for (int im = 0; im < 4; im++) {
#pragma unroll
                for (int jn = 0; jn < 4; jn++) {
                    uint32_t b0 = bf[jn >> 1][(jn & 1) * 2 + 0];
                    uint32_t b1 = bf[jn >> 1][(jn & 1) * 2 + 1];
                    MMA16816(acc[im * 4 + jn], af[im], b0, b1);
                }
            }
        }
        __syncthreads();

        int t = s + 3;
        if (t < NSTAGE) load_stage(t, tid, mBase, nBase, smem_base, Wh, Wl);
    }

    // epilogue
    int q = lane >> 2, rpair = lane & 3;
#pragma unroll
    for (int im = 0; im < 4; im++) {
        int r0 = mBase + warp_m * 64 + im * 16 + q;
        int r1 = r0 + 8;
#pragma unroll
        for (int jn = 0; jn < 4; jn++) {
            int col = nBase + warp_n * 32 + jn * 8 + rpair * 2;
            float* c = acc[im * 4 + jn];
            if (r0 < NN) *(float2*)(C + (size_t)r0 * HD + col) = make_float2(c[0], c[1]);
            if (r1 < NN) *(float2*)(C + (size_t)r1 * HD + col) = make_float2(c[2], c[3]);
        }
    }
}

// ---------------- per-node scalars: warp per (n,h) --------------------------
__global__ void node_scalar(const float* __restrict__ a) {
    int gw = (blockIdx.x * blockDim.x + threadIdx.x) >> 5;
    int lane = threadIdx.x & 31;
    if (gw >= NN * HH) return;
    int n = gw >> 3, h = gw & 7;
    const float* he = g_he + (size_t)n * HD + h * DD;
    const float* hr = g_hr + (size_t)n * HD + h * DD;
    const float* ah = a + h * (5 * DD);

    float s1 = he[lane] * ah[lane] + he[lane + 32] * ah[lane + 32];
    float s2 = he[lane] * ah[DD + lane] + he[lane + 32] * ah[DD + lane + 32];
    float s3 = hr[lane] * ah[2 * DD + lane] + hr[lane + 32] * ah[2 * DD + lane + 32];
#pragma unroll
    for (int o = 16; o; o >>= 1) {
        s1 += __shfl_xor_sync(0xffffffffu, s1, o);
        s2 += __shfl_xor_sync(0xffffffffu, s2, o);
        s3 += __shfl_xor_sync(0xffffffffu, s3, o);
    }
    if (lane == 0) {
        g_sS[n * HH + h] = s1;
        g_sD[n * HH + h] = s2;
        g_pD[n * HH + h] = s3;
    }
}

// ---------------- CSR build ----------------
__global__ void zero_deg() {
    int i = blockIdx.x * blockDim.x + threadIdx.x;
    if (i < NN) g_deg[i] = 0;
}

__global__ void hist_k(const void* __restrict__ ei) {
    int e = blockIdx.x * blockDim.x + threadIdx.x;
    if (e >= EE) return;
    atomicAdd(&g_deg[load_idx(ei, 0, e)], 1);
}

__global__ void scan_k() {
    __shared__ int wsum[32];
    __shared__ int s_carry;
    int tid = threadIdx.x, lane = tid & 31, wid = tid >> 5;
    if (tid == 0) s_carry = 0;
    __syncthreads();
    for (int base = 0; base < NN; base += 1024) {
        int i = base + tid;
        int x = (i < NN) ? g_deg[i] : 0;
#pragma unroll
        for (int o = 1; o < 32; o <<= 1) {
            int t = __shfl_up_sync(0xffffffffu, x, o);
            if (lane >= o) x += t;
        }
        if (lane == 31) wsum[wid] = x;
        __syncthreads();
        if (wid == 0) {
            int y = wsum[lane];
#pragma unroll
            for (int o = 1; o < 32; o <<= 1) {
                int t = __shfl_up_sync(0xffffffffu, y, o);
                if (lane >= o) y += t;
            }
            wsum[lane] = y;
        }
        __syncthreads();
        int c = s_carry;
        int incl = x + (wid ? wsum[wid - 1] : 0) + c;
        if (i < NN) g_off[i + 1] = incl;
        __syncthreads();
        if (tid == 1023) s_carry = incl;
        __syncthreads();
    }
    if (threadIdx.x == 0) g_off[0] = 0;
}

__global__ void copy_cur() {
    int i = blockIdx.x * blockDim.x + threadIdx.x;
    if (i < NN) g_cur[i] = g_off[i];
}

__global__ void scatter_k(const void* __restrict__ ei) {
    int e = blockIdx.x * blockDim.x + threadIdx.x;
    if (e >= EE) return;
    int s = load_idx(ei, 0, e);
    int t = load_idx(ei, 1, e);
    int p = atomicAdd(&g_cur[s], 1);
    g_srcs[p] = s;
    g_dsts[p] = t;
}

// ---------------- per-edge scores (warp per edge, coalesced rows) -----------
__global__ __launch_bounds__(256) void score_k(const float* __restrict__ a) {
    __shared__ float sAbs[HD], sPrd[HD];
    int tid = threadIdx.x;
    for (int i = tid; i < HD; i += 256) {
        int h = i >> 6, d = i & 63;
        sAbs[i] = a[h * 320 + 3 * DD + d];
        sPrd[i] = a[h * 320 + 4 * DD + d];
    }
    __syncthreads();

    int p = blockIdx.x * 8 + (tid >> 5);
    int lane = tid & 31;
    if (p >= EE) return;
    int s = g_srcs[p], t = g_dsts[p];
    const float* rs = g_hr + (size_t)s * HD;
    const float* rt = g_hr + (size_t)t * HD;

    float accA[8], accP[8];
#pragma unroll
    for (int h = 0; h < 8; h++) { accA[h] = 0.f; accP[h] = 0.f; }

#pragma unroll
    for (int k = 0; k < 16; k++) {
        int i = lane + 32 * k;
        float vs = rs[i], vt = rt[i];
        float df = vt - vs;
        int h = k >> 1;          // compile-time per unrolled iter
        accA[h] = fmaf(sAbs[i], fabsf(df), accA[h]);
        accP[h] = fmaf(sPrd[i] * vs, vt, accP[h]);
    }

    float myA = 0.f, myP = 0.f;
#pragma unroll
    for (int h = 0; h < 8; h++) {
        float va = accA[h], vp = accP[h];
#pragma unroll
        for (int o = 16; o; o >>= 1) {
            va += __shfl_xor_sync(0xffffffffu, va, o);
            vp += __shfl_xor_sync(0xffffffffu, vp, o);
        }
        if (lane == h) { myA = va; myP = vp; }
    }

    if (lane < 8) {
        int h = lane;
        float sc = g_sS[s * HH + h] + g_sD[t * HH + h] + g_pD[t * HH + h]
                 - g_pD[s * HH + h] + myA + myP;
        float al = sc > 0.f ? sc : LRELU * sc;
        g_att[p * 8 + h] = al;           // [edge][head] layout
    }
}

// ---------------- segment softmax: warp per node, all heads at once ---------
__global__ void softmax_k() {
    int w = (blockIdx.x * blockDim.x + threadIdx.x) >> 5;
    int lane = threadIdx.x & 31;
    if (w >= NN) return;
    int b8 = g_off[w] * 8, e8 = g_off[w + 1] * 8;
    if (b8 == e8) return;

    // lane's head = lane & 7 (stride 32 preserves h since 8 | 32)
    float m = -3.4e38f;
    for (int i = b8 + lane; i < e8; i += 32) m = fmaxf(m, g_att[i]);
    m = fmaxf(m, __shfl_xor_sync(0xffffffffu, m, 8));
    m = fmaxf(m, __shfl_xor_sync(0xffffffffu, m, 16));

    float sum = 0.f;
    for (int i = b8 + lane; i < e8; i += 32) {
        float e = expf(g_att[i] - m);
        g_att[i] = e;
        sum += e;
    }
    sum += __shfl_xor_sync(0xffffffffu, sum, 8);
    sum += __shfl_xor_sync(0xffffffffu, sum, 16);
    float inv = 1.f / (sum + EPSV);
    for (int i = b8 + lane; i < e8; i += 32) g_att[i] *= inv;
}

// ---------------- aggregation: block per node, float4 per thread ------------
__global__ __launch_bounds__(128) void agg_k(float* __restrict__ out) {
    int n = blockIdx.x;
    int tid = threadIdx.x;
    int h = tid >> 4;                 // (tid*4) / 64
    int beg = g_off[n], end = g_off[n + 1];
    float4 acc = make_float4(0.f, 0.f, 0.f, 0.f);
    for (int p = beg; p < end; p++) {
        int t = g_dsts[p];
        float av = g_att[p * 8 + h];
        float4 v = ((const float4*)(g_he + (size_t)t * HD))[tid];
        acc.x = fmaf(av, v.x, acc.x);
        acc.y = fmaf(av, v.y, acc.y);
        acc.z = fmaf(av, v.z, acc.z);
        acc.w = fmaf(av, v.w, acc.w);
    }
    ((float4*)(out + (size_t)n * HD))[tid] = acc;
}

// ---------------- launch ----------------
extern "C" void kernel_launch(void* const* d_in, const int* in_sizes, int n_in,
                              void* d_out, int out_size) {
    const float* x  = (const float*)d_in[0];
    const void*  ei = d_in[1];
    const float* We = (const float*)d_in[2];
    const float* Wr = (const float*)d_in[3];
    const float* a  = (const float*)d_in[4];
    float* out = (float*)d_out;

    static int smem_set = 0;
    if (!smem_set) {
        cudaFuncSetAttribute(mma_k, cudaFuncAttributeMaxDynamicSharedMemorySize,
                             3 * STAGE_BYTES);
        smem_set = 1;
    }

    detect_k<<<1, 32>>>((const int*)ei);
    prep_wb<<<(2 * FF * HD + 255) / 256, 256>>>(We, Wr);
    cvt_x<<<(NN * FF / 4 + 255) / 256, 256>>>(x);

    dim3 gg((NN + TM - 1) / TM, HD / TN, 2);
    mma_k<<<gg, 256, 3 * STAGE_BYTES>>>();

    node_scalar<<<(NN * HH * 32 + 255) / 256, 256>>>(a);

    zero_deg<<<(NN + 255) / 256, 256>>>();
    hist_k<<<(EE + 255) / 256, 256>>>(ei);
    scan_k<<<1, 1024>>>();
    copy_cur<<<(NN + 255) / 256, 256>>>();
    scatter_k<<<(EE + 255) / 256, 256>>>(ei);

    score_k<<<(EE + 7) / 8, 256>>>(a);
    softmax_k<<<(NN * 32 + 255) / 256, 256>>>();
    agg_k<<<NN, 128>>>(out);
}

// round 17
// speedup vs baseline: 2.1292x; 1.2018x over previous
#include <cuda_runtime.h>
#include <cuda_bf16.h>
#include <cstdint>

#define NN 20000
#define EE 320000
#define FF 512
#define HH 8
#define DD 64
#define HD 512           // HH*DD
#define LRELU 0.2f
#define EPSV 1e-16f

#define TM 128
#define TN 128
#define A_BYTES 32768            // 128 rows x 128 bf16 (two 128B half-rows)
#define STAGE_BYTES 65536        // A tile + B tile
#define NSTAGE 12                // 4 K-chunks(128) x 3 hi/lo combos

// ---------------- scratch (static device globals; no allocs) ----------------
__device__ float g_he[NN * HD];
__device__ float g_hr[NN * HD];
__device__ __nv_bfloat16 g_xh[NN * FF];
__device__ __nv_bfloat16 g_xl[NN * FF];
__device__ __nv_bfloat16 g_Wbh[2][FF * HD];   // [mat][n][k]  (n = h*64+d, k = f)
__device__ __nv_bfloat16 g_Wbl[2][FF * HD];
__device__ float g_sS[NN * HH];
__device__ float g_sD[NN * HH];
__device__ float g_pD[NN * HH];
__device__ int   g_deg[NN];
__device__ int   g_off[NN + 1];
__device__ int   g_cur[NN];
__device__ int   g_srcs[EE];
__device__ int   g_dsts[EE];
__device__ float g_att[EE * HH];   // layout [edge][head]
__device__ int   g_is64;

// ---------------- small helpers ----------------
__device__ __forceinline__ uint32_t smem_u32(const void* p) {
    uint32_t a;
    asm("{ .reg .u64 t; cvta.to.shared.u64 t, %1; cvt.u32.u64 %0, t; }" : "=r"(a) : "l"(p));
    return a;
}

__device__ __forceinline__ void cp16(uint32_t dst, const void* src, int srcsize) {
    asm volatile("cp.async.cg.shared.global [%0], [%1], 16, %2;"
                 :: "r"(dst), "l"(src), "r"(srcsize) : "memory");
}

#define SWZ(o) ((o) ^ (((o) >> 3) & 0x70))

#define LDSM4(r, a) \
    asm volatile("ldmatrix.sync.aligned.m8n8.x4.shared.b16 {%0,%1,%2,%3}, [%4];" \
                 : "=r"((r)[0]), "=r"((r)[1]), "=r"((r)[2]), "=r"((r)[3]) : "r"(a))

#define MMA16816(c, a, b0, b1) \
    asm volatile("mma.sync.aligned.m16n8k16.row.col.f32.bf16.bf16.f32 " \
                 "{%0,%1,%2,%3},{%4,%5,%6,%7},{%8,%9},{%0,%1,%2,%3};" \
                 : "+f"((c)[0]), "+f"((c)[1]), "+f"((c)[2]), "+f"((c)[3]) \
                 : "r"((a)[0]), "r"((a)[1]), "r"((a)[2]), "r"((a)[3]), \
                   "r"(b0), "r"(b1))

// ---------------- dtype probe ----------------
__global__ void detect_k(const int* __restrict__ w) {
    if (threadIdx.x == 0 && blockIdx.x == 0) {
        int ornz = 0;
        for (int i = 1; i < 256; i += 2) ornz |= w[i];
        g_is64 = (ornz == 0) ? 1 : 0;
    }
}

__device__ __forceinline__ int load_idx(const void* ei, int which, int e) {
    if (g_is64) return (int)((const long long*)ei)[(long)which * EE + e];
    return ((const int*)ei)[which * EE + e];
}

// ---------------- x -> bf16 hi/lo ----------------
__global__ void cvt_x(const float* __restrict__ x) {
    int i = blockIdx.x * blockDim.x + threadIdx.x;
    if (i >= NN * FF / 4) return;
    float4 v = ((const float4*)x)[i];
    __nv_bfloat16 h0 = __float2bfloat16_rn(v.x);
    __nv_bfloat16 h1 = __float2bfloat16_rn(v.y);
    __nv_bfloat16 h2 = __float2bfloat16_rn(v.z);
    __nv_bfloat16 h3 = __float2bfloat16_rn(v.w);
    __nv_bfloat16 l0 = __float2bfloat16_rn(v.x - __bfloat162float(h0));
    __nv_bfloat16 l1 = __float2bfloat16_rn(v.y - __bfloat162float(h1));
    __nv_bfloat16 l2 = __float2bfloat16_rn(v.z - __bfloat162float(h2));
    __nv_bfloat16 l3 = __float2bfloat16_rn(v.w - __bfloat162float(h3));
    ((__nv_bfloat162*)g_xh)[i * 2 + 0] = __nv_bfloat162(h0, h1);
    ((__nv_bfloat162*)g_xh)[i * 2 + 1] = __nv_bfloat162(h2, h3);
    ((__nv_bfloat162*)g_xl)[i * 2 + 0] = __nv_bfloat162(l0, l1);
    ((__nv_bfloat162*)g_xl)[i * 2 + 1] = __nv_bfloat162(l2, l3);
}

// ---------------- W -> bf16 hi/lo, transposed to [n][k] ---------------------
__global__ void prep_wb(const float* __restrict__ We, const float* __restrict__ Wr) {
    int idx = blockIdx.x * blockDim.x + threadIdx.x;
    if (idx >= 2 * FF * HD) return;
    int which = idx / (FF * HD);
    int rem = idx - which * (FF * HD);
    int n = rem >> 9;
    int k = rem & 511;
    int h = n >> 6, d = n & 63;
    const float* W = which ? Wr : We;
    float v = W[h * (FF * DD) + k * DD + d];
    __nv_bfloat16 hi = __float2bfloat16_rn(v);
    __nv_bfloat16 lo = __float2bfloat16_rn(v - __bfloat162float(hi));
    g_Wbh[which][n * FF + k] = hi;
    g_Wbl[which][n * FF + k] = lo;
}

// ---------------- stage loader: A 128x128bf16 + B 128x128bf16 ---------------
__device__ __forceinline__ void load_stage(int s, int tid, int mBase, int nBase,
                                           uint32_t smem_base,
                                           const __nv_bfloat16* Wh,
                                           const __nv_bfloat16* Wl) {
    int combo = s >> 2, kc2 = s & 3;
    const __nv_bfloat16* Asrc = (combo < 2) ? g_xh : g_xl;
    const __nv_bfloat16* Bsrc = (combo == 1) ? Wl : Wh;
    uint32_t abase = smem_base + (s % 3) * STAGE_BYTES;
    uint32_t bbase = abase + A_BYTES;
#pragma unroll
    for (int i = tid; i < 2048; i += 256) {
        int row = i >> 4, r = i & 15, half = r >> 3, c = r & 7;
        int gm = mBase + row;
        uint32_t dst = abase + half * 16384 + SWZ(row * 128 + c * 16);
        size_t off = (gm < NN) ? ((size_t)gm * 1024 + kc2 * 256 + half * 128 + c * 16) : 0;
        cp16(dst, (const char*)Asrc + off, gm < NN ? 16 : 0);
    }
#pragma unroll
    for (int i = tid; i < 2048; i += 256) {
        int row = i >> 4, r = i & 15, half = r >> 3, c = r & 7;
        int n = nBase + row;
        uint32_t dst = bbase + half * 16384 + SWZ(row * 128 + c * 16);
        cp16(dst, (const char*)Bsrc + ((size_t)n * 1024 + kc2 * 256 + half * 128 + c * 16), 16);
    }
    asm volatile("cp.async.commit_group;" ::: "memory");
}

// ---------------- bf16 mma.sync GEMM: C = xh*Wh + xh*Wl + xl*Wh -------------
__global__ __launch_bounds__(256, 1) void mma_k() {
    extern __shared__ char smem[];
    int tid = threadIdx.x, wid = tid >> 5, lane = tid & 31;
    int mBase = blockIdx.x * TM;
    int nBase = blockIdx.y * TN;
    int mat = blockIdx.z;
    const __nv_bfloat16* Wh = g_Wbh[mat];
    const __nv_bfloat16* Wl = g_Wbl[mat];
    float* C = mat ? g_hr : g_he;

    uint32_t smem_base = smem_u32(smem);

    int warp_m = wid >> 2;
    int warp_n = wid & 3;
    int g = lane >> 3, lr = lane & 7;

    int arow = warp_m * 64 + (g & 1) * 8 + lr;
    int abyt = (g >> 1) * 16;
    int brow = warp_n * 32 + (g >> 1) * 8 + lr;
    int bbyt = (g & 1) * 16;

    float acc[16][4];
#pragma unroll
    for (int i = 0; i < 16; i++)
#pragma unroll
        for (int j = 0; j < 4; j++) acc[i][j] = 0.f;

    load_stage(0, tid, mBase, nBase, smem_base, Wh, Wl);
    load_stage(1, tid, mBase, nBase, smem_base, Wh, Wl);
    load_stage(2, tid, mBase, nBase, smem_base, Wh, Wl);

    for (int s = 0; s < NSTAGE; s++) {
        if (s <= NSTAGE - 3)      asm volatile("cp.async.wait_group 2;" ::: "memory");
        else if (s == NSTAGE - 2) asm volatile("cp.async.wait_group 1;" ::: "memory");
        else                      asm volatile("cp.async.wait_group 0;" ::: "memory");
        __syncthreads();

        uint32_t abase = smem_base + (s % 3) * STAGE_BYTES;
        uint32_t bbase = abase + A_BYTES;

        uint32_t af[2][4][4], bf[2][2][4];
#pragma unroll
        for (int im = 0; im < 4; im++)
            LDSM4(af[0][im], abase + SWZ((arow + im * 16) * 128 + abyt));
#pragma unroll
        for (int jp = 0; jp < 2; jp++)
            LDSM4(bf[0][jp], bbase + SWZ((brow + jp * 16) * 128 + bbyt));

#pragma unroll
        for (int ks = 0; ks < 8; ks++) {
            int cur = ks & 1, nxt = cur ^ 1;
            if (ks < 7) {
                int k2 = ks + 1;
                uint32_t ab = abase + (k2 >> 2) * 16384;
                uint32_t bb = bbase + (k2 >> 2) * 16384;
                int ksi = k2 & 3;
#pragma unroll
                for (int im = 0; im < 4; im++)
                    LDSM4(af[nxt][im], ab + SWZ((arow + im * 16) * 128 + ksi * 32 + abyt));
#pragma unroll
                for (int jp = 0; jp < 2; jp++)
                    LDSM4(bf[nxt][jp], bb + SWZ((brow + jp * 16) * 128 + ksi * 32 + bbyt));
            }
#pragma unroll
            for (int im = 0; im < 4; im++) {
#pragma unroll
                for (int jn = 0; jn < 4; jn++) {
                    uint32_t b0 = bf[cur][jn >> 1][(jn & 1) * 2 + 0];
                    uint32_t b1 = bf[cur][jn >> 1][(jn & 1) * 2 + 1];
                    MMA16816(acc[im * 4 + jn], af[cur][im], b0, b1);
                }
            }
        }
        __syncthreads();

        int t = s + 3;
        if (t < NSTAGE) load_stage(t, tid, mBase, nBase, smem_base, Wh, Wl);
    }

    int q = lane >> 2, rpair = lane & 3;
#pragma unroll
    for (int im = 0; im < 4; im++) {
        int r0 = mBase + warp_m * 64 + im * 16 + q;
        int r1 = r0 + 8;
#pragma unroll
        for (int jn = 0; jn < 4; jn++) {
            int col = nBase + warp_n * 32 + jn * 8 + rpair * 2;
            float* c = acc[im * 4 + jn];
            if (r0 < NN) *(float2*)(C + (size_t)r0 * HD + col) = make_float2(c[0], c[1]);
            if (r1 < NN) *(float2*)(C + (size_t)r1 * HD + col) = make_float2(c[2], c[3]);
        }
    }
}

// ---------------- per-node scalars: warp per (n,h) --------------------------
__global__ void node_scalar(const float* __restrict__ a) {
    int gw = (blockIdx.x * blockDim.x + threadIdx.x) >> 5;
    int lane = threadIdx.x & 31;
    if (gw >= NN * HH) return;
    int n = gw >> 3, h = gw & 7;
    const float* he = g_he + (size_t)n * HD + h * DD;
    const float* hr = g_hr + (size_t)n * HD + h * DD;
    const float* ah = a + h * (5 * DD);

    float s1 = he[lane] * ah[lane] + he[lane + 32] * ah[lane + 32];
    float s2 = he[lane] * ah[DD + lane] + he[lane + 32] * ah[DD + lane + 32];
    float s3 = hr[lane] * ah[2 * DD + lane] + hr[lane + 32] * ah[2 * DD + lane + 32];
#pragma unroll
    for (int o = 16; o; o >>= 1) {
        s1 += __shfl_xor_sync(0xffffffffu, s1, o);
        s2 += __shfl_xor_sync(0xffffffffu, s2, o);
        s3 += __shfl_xor_sync(0xffffffffu, s3, o);
    }
    if (lane == 0) {
        g_sS[n * HH + h] = s1;
        g_sD[n * HH + h] = s2;
        g_pD[n * HH + h] = s3;
    }
}

// ---------------- CSR build ----------------
__global__ void zero_deg() {
    int i = blockIdx.x * blockDim.x + threadIdx.x;
    if (i < NN) g_deg[i] = 0;
}

__global__ void hist_k(const void* __restrict__ ei) {
    int e = blockIdx.x * blockDim.x + threadIdx.x;
    if (e >= EE) return;
    atomicAdd(&g_deg[load_idx(ei, 0, e)], 1);
}

// scan also writes g_cur (exclusive prefix) so copy_cur is not needed
__global__ void scan_k() {
    __shared__ int wsum[32];
    __shared__ int s_carry;
    int tid = threadIdx.x, lane = tid & 31, wid = tid >> 5;
    if (tid == 0) s_carry = 0;
    __syncthreads();
    for (int base = 0; base < NN; base += 1024) {
        int i = base + tid;
        int x = (i < NN) ? g_deg[i] : 0;
        int xorig = x;
#pragma unroll
        for (int o = 1; o < 32; o <<= 1) {
            int t = __shfl_up_sync(0xffffffffu, x, o);
            if (lane >= o) x += t;
        }
        if (lane == 31) wsum[wid] = x;
        __syncthreads();
        if (wid == 0) {
            int y = wsum[lane];
#pragma unroll
            for (int o = 1; o < 32; o <<= 1) {
                int t = __shfl_up_sync(0xffffffffu, y, o);
                if (lane >= o) y += t;
            }
            wsum[lane] = y;
        }
        __syncthreads();
        int c = s_carry;
        int incl = x + (wid ? wsum[wid - 1] : 0) + c;
        if (i < NN) {
            g_off[i + 1] = incl;
            g_cur[i] = incl - xorig;
        }
        __syncthreads();
        if (tid == 1023) s_carry = incl;
        __syncthreads();
    }
    if (threadIdx.x == 0) g_off[0] = 0;
}

__global__ void scatter_k(const void* __restrict__ ei) {
    int e = blockIdx.x * blockDim.x + threadIdx.x;
    if (e >= EE) return;
    int s = load_idx(ei, 0, e);
    int t = load_idx(ei, 1, e);
    int p = atomicAdd(&g_cur[s], 1);
    g_srcs[p] = s;
    g_dsts[p] = t;
}

// ---------------- per-edge scores: CSR warp-per-node ------------------------
// j = lane + 32k (float4 idx), head = 2k + (lane>>4), d = 4*(lane&15).
__global__ __launch_bounds__(256) void score_k(const float* __restrict__ a) {
    int w = (blockIdx.x * 256 + threadIdx.x) >> 5;   // node
    int lane = threadIdx.x & 31;
    if (w >= NN) return;
    int hb = lane >> 4;
    int d = 4 * (lane & 15);

    float4 aA[4], aP[4], rsv[4];
    float sBase[4];
    const float4* rs4 = (const float4*)(g_hr + (size_t)w * HD);
#pragma unroll
    for (int k = 0; k < 4; k++) {
        int h = 2 * k + hb;
        aA[k] = *(const float4*)(a + h * 320 + 3 * DD + d);
        aP[k] = *(const float4*)(a + h * 320 + 4 * DD + d);
        rsv[k] = rs4[lane + 32 * k];
        sBase[k] = g_sS[w * HH + h] - g_pD[w * HH + h];
    }

    int beg = g_off[w], end = g_off[w + 1];
    for (int p = beg; p < end; p++) {
        int t = g_dsts[p];
        const float4* rt4 = (const float4*)(g_hr + (size_t)t * HD);
        float acc[4];
#pragma unroll
        for (int k = 0; k < 4; k++) {
            float4 vt = rt4[lane + 32 * k];
            float4 vs = rsv[k];
            float s = aA[k].x * fabsf(vt.x - vs.x);
            s = fmaf(aA[k].y, fabsf(vt.y - vs.y), s);
            s = fmaf(aA[k].z, fabsf(vt.z - vs.z), s);
            s = fmaf(aA[k].w, fabsf(vt.w - vs.w), s);
            s = fmaf(aP[k].x * vs.x, vt.x, s);
            s = fmaf(aP[k].y * vs.y, vt.y, s);
            s = fmaf(aP[k].z * vs.z, vt.z, s);
            s = fmaf(aP[k].w * vs.w, vt.w, s);
            acc[k] = s;
        }
#pragma unroll
        for (int o = 1; o < 16; o <<= 1) {
#pragma unroll
            for (int k = 0; k < 4; k++)
                acc[k] += __shfl_xor_sync(0xffffffffu, acc[k], o);
        }
        if ((lane & 15) == 0) {
#pragma unroll
            for (int k = 0; k < 4; k++) {
                int h = 2 * k + hb;
                float sc = sBase[k] + g_sD[t * HH + h] + g_pD[t * HH + h] + acc[k];
                g_att[p * 8 + h] = sc > 0.f ? sc : LRELU * sc;
            }
        }
    }
}

// ---------------- segment softmax: warp per node, all heads at once ---------
__global__ void softmax_k() {
    int w = (blockIdx.x * blockDim.x + threadIdx.x) >> 5;
    int lane = threadIdx.x & 31;
    if (w >= NN) return;
    int b8 = g_off[w] * 8, e8 = g_off[w + 1] * 8;
    if (b8 == e8) return;

    float m = -3.4e38f;
    for (int i = b8 + lane; i < e8; i += 32) m = fmaxf(m, g_att[i]);
    m = fmaxf(m, __shfl_xor_sync(0xffffffffu, m, 8));
    m = fmaxf(m, __shfl_xor_sync(0xffffffffu, m, 16));

    float sum = 0.f;
    for (int i = b8 + lane; i < e8; i += 32) {
        float e = expf(g_att[i] - m);
        g_att[i] = e;
        sum += e;
    }
    sum += __shfl_xor_sync(0xffffffffu, sum, 8);
    sum += __shfl_xor_sync(0xffffffffu, sum, 16);
    float inv = 1.f / (sum + EPSV);
    for (int i = b8 + lane; i < e8; i += 32) g_att[i] *= inv;
}

// ---------------- aggregation: block per node, float4 per thread ------------
__global__ __launch_bounds__(128) void agg_k(float* __restrict__ out) {
    int n = blockIdx.x;
    int tid = threadIdx.x;
    int h = tid >> 4;
    int beg = g_off[n], end = g_off[n + 1];
    float4 acc = make_float4(0.f, 0.f, 0.f, 0.f);
    for (int p = beg; p < end; p++) {
        int t = g_dsts[p];
        float av = g_att[p * 8 + h];
        float4 v = ((const float4*)(g_he + (size_t)t * HD))[tid];
        acc.x = fmaf(av, v.x, acc.x);
        acc.y = fmaf(av, v.y, acc.y);
        acc.z = fmaf(av, v.z, acc.z);
        acc.w = fmaf(av, v.w, acc.w);
    }
    ((float4*)(out + (size_t)n * HD))[tid] = acc;
}

// ---------------- launch ----------------
extern "C" void kernel_launch(void* const* d_in, const int* in_sizes, int n_in,
                              void* d_out, int out_size) {
    const float* x  = (const float*)d_in[0];
    const void*  ei = d_in[1];
    const float* We = (const float*)d_in[2];
    const float* Wr = (const float*)d_in[3];
    const float* a  = (const float*)d_in[4];
    float* out = (float*)d_out;

    static int smem_set = 0;
    if (!smem_set) {
        cudaFuncSetAttribute(mma_k, cudaFuncAttributeMaxDynamicSharedMemorySize,
                             3 * STAGE_BYTES);
        smem_set = 1;
    }

    detect_k<<<1, 32>>>((const int*)ei);
    prep_wb<<<(2 * FF * HD + 255) / 256, 256>>>(We, Wr);
    cvt_x<<<(NN * FF / 4 + 255) / 256, 256>>>(x);

    dim3 gg((NN + TM - 1) / TM, HD / TN, 2);
    mma_k<<<gg, 256, 3 * STAGE_BYTES>>>();

    node_scalar<<<(NN * HH * 32 + 255) / 256, 256>>>(a);

    zero_deg<<<(NN + 255) / 256, 256>>>();
    hist_k<<<(EE + 255) / 256, 256>>>(ei);
    scan_k<<<1, 1024>>>();
    scatter_k<<<(EE + 255) / 256, 256>>>(ei);

    score_k<<<(NN * 32 + 255) / 256, 256>>>(a);
    softmax_k<<<(NN * 32 + 255) / 256, 256>>>();
    agg_k<<<NN, 128>>>(out);
}